// round 1
// baseline (speedup 1.0000x reference)
#include <cuda_runtime.h>
#include <math.h>

// Problem constants
#define TT 1000
#define BB 32
#define NN 2048
#define BN (BB * NN)            // 65536
// Output layout (concatenated tuple, all f32):
// [0, 65536)        firing_rates
// [65536, 131072)   cv_isi
// [131072, 131104)  synchrony
// [131104, 196640)  total_spikes
// [196640, 196672)  active_neurons
#define OFF_FR 0
#define OFF_CV 65536
#define OFF_SY 131072
#define OFF_TS 131104
#define OFF_AN 196640

// Scratch (overwritten every launch; no init needed)
__device__ float g_pop_part[256 * TT];   // per-block population partials [bid][t]
__device__ float g_active_part[256];     // per-block active-neuron partials

__global__ __launch_bounds__(256, 2)
void spike_main(const float* __restrict__ in, float* __restrict__ out) {
    const int bid  = blockIdx.x;          // 0..255
    const int tid  = threadIdx.x;         // 0..255
    const int b    = bid >> 3;            // 8 blocks per batch
    const int n    = ((bid & 7) << 8) | tid;
    const int w    = tid >> 5;
    const int lane = tid & 31;

    __shared__ float pop_s[8][TT];        // 32 KB: per-warp population rows
    __shared__ int   active_s[8];

    const float* p = in + (size_t)b * NN + n;   // stride BN per timestep

    int last = -1, first = 0, total = 0, sumg2 = 0;

    #pragma unroll 1
    for (int t = 0; t < TT; t += 4) {
        // batch 4 independent loads (MLP=4)
        float x0 = p[(size_t)(t + 0) * BN];
        float x1 = p[(size_t)(t + 1) * BN];
        float x2 = p[(size_t)(t + 2) * BN];
        float x3 = p[(size_t)(t + 3) * BN];
        float xv[4] = {x0, x1, x2, x3};
        #pragma unroll
        for (int j = 0; j < 4; j++) {
            bool s = xv[j] > 0.5f;
            unsigned m = __ballot_sync(0xffffffffu, s);
            if (lane == 0) pop_s[w][t + j] = (float)__popc(m);
            if (s) {
                int tt = t + j;
                if (last >= 0) {
                    int g = tt - last;
                    sumg2 += g * g;
                } else {
                    first = tt;
                }
                last = tt;
                total++;
            }
        }
    }

    // Per-neuron outputs
    const int idx = b * NN + n;
    float tot = (float)total;
    out[OFF_FR + idx] = tot / (TT * 0.001f);   // firing rate (Hz)
    out[OFF_TS + idx] = tot;                   // total spikes

    float cv = 0.0f;
    int cnt = total - 1;                       // spikes with a predecessor
    if (cnt >= 1) {
        float fc   = (float)cnt;
        float mean = (float)(last - first) / fc;     // sum of gaps / cnt
        float var  = ((float)sumg2 - fc * mean * mean) / fmaxf(fc - 1.0f, 1.0f);
        cv = sqrtf(fmaxf(var, 0.0f)) / fmaxf(mean, 1e-12f);
    }
    out[OFF_CV + idx] = cv;

    // Active-neuron count: warp ballot -> block partial
    unsigned am = __ballot_sync(0xffffffffu, total > 0);
    if (lane == 0) active_s[w] = __popc(am);
    __syncthreads();
    if (tid == 0) {
        int a = 0;
        #pragma unroll
        for (int k = 0; k < 8; k++) a += active_s[k];
        g_active_part[bid] = (float)a;
    }

    // Reduce 8 warp rows -> per-block population partial
    for (int t = tid; t < TT; t += 256) {
        float s = 0.0f;
        #pragma unroll
        for (int k = 0; k < 8; k++) s += pop_s[k][t];
        g_pop_part[bid * TT + t] = s;
    }
}

__global__ __launch_bounds__(256)
void spike_sync(float* __restrict__ out) {
    const int b   = blockIdx.x;    // 0..31
    const int tid = threadIdx.x;

    __shared__ float  pop[TT];
    __shared__ double red[256];

    // Assemble pop[t] for this batch from the 8 block partials
    for (int t = tid; t < TT; t += 256) {
        float s = 0.0f;
        #pragma unroll
        for (int k = 0; k < 8; k++) s += g_pop_part[(b * 8 + k) * TT + t];
        pop[t] = s;
    }
    __syncthreads();

    // mean
    double ls = 0.0;
    for (int t = tid; t < TT; t += 256) ls += (double)pop[t];
    red[tid] = ls;
    __syncthreads();
    for (int o = 128; o > 0; o >>= 1) {
        if (tid < o) red[tid] += red[tid + o];
        __syncthreads();
    }
    double mean = red[0] / (double)TT;
    __syncthreads();

    // circular lag-1 autocorrelation: num = sum xm[t]*xm[t-1], den = sum xm^2
    double lnum = 0.0, lden = 0.0;
    for (int t = tid; t < TT; t += 256) {
        double xm = (double)pop[t] - mean;
        int tp = (t == 0) ? (TT - 1) : (t - 1);
        double ym = (double)pop[tp] - mean;
        lnum += xm * ym;
        lden += xm * xm;
    }
    red[tid] = lnum;
    __syncthreads();
    for (int o = 128; o > 0; o >>= 1) {
        if (tid < o) red[tid] += red[tid + o];
        __syncthreads();
    }
    double num = red[0];
    __syncthreads();
    red[tid] = lden;
    __syncthreads();
    for (int o = 128; o > 0; o >>= 1) {
        if (tid < o) red[tid] += red[tid + o];
        __syncthreads();
    }
    double den = red[0];

    if (tid == 0) {
        out[OFF_SY + b] = (den > 0.0) ? (float)(num / fmax(den, 1e-12)) : 0.0f;
        float a = 0.0f;
        #pragma unroll
        for (int k = 0; k < 8; k++) a += g_active_part[b * 8 + k];
        out[OFF_AN + b] = a;
    }
}

extern "C" void kernel_launch(void* const* d_in, const int* in_sizes, int n_in,
                              void* d_out, int out_size) {
    const float* in = (const float*)d_in[0];
    float* out = (float*)d_out;
    spike_main<<<256, 256>>>(in, out);
    spike_sync<<<BB, 256>>>(out);
}

// round 2
// speedup vs baseline: 2.8741x; 2.8741x over previous
#include <cuda_runtime.h>
#include <math.h>

// Problem constants
#define TT 1000
#define BB 32
#define NN 2048
#define BN (BB * NN)            // 65536
#define UU 20                   // timesteps per group (1000 = 20 * 50)
// Output layout (concatenated tuple, all f32):
#define OFF_FR 0
#define OFF_CV 65536
#define OFF_SY 131072
#define OFF_TS 131104
#define OFF_AN 196640

// Scratch (overwritten every launch; no init needed)
__device__ float g_pop_part[256 * TT];   // per-block population partials [bid][t]
__device__ float g_active_part[256];     // per-block active-neuron partials

__global__ __launch_bounds__(256, 2)
void spike_main(const float* __restrict__ in, float* __restrict__ out) {
    const int bid  = blockIdx.x;          // 0..255
    const int tid  = threadIdx.x;         // 0..255
    const int b    = bid >> 3;            // 8 blocks per batch
    const int n    = ((bid & 7) << 8) | tid;
    const int w    = tid >> 5;
    const int lane = tid & 31;

    __shared__ float pop_s[8][TT];        // 32 KB: per-warp population rows
    __shared__ int   active_s[8];

    const float* p = in + (size_t)b * NN + n;   // stride BN per timestep

    int last = -1, first = 0, total = 0, sumg2 = 0;

    float cur[UU], nxt[UU];

    // Prime the pipeline: group 0
    #pragma unroll
    for (int i = 0; i < UU; i++) cur[i] = p[(size_t)i * BN];

    #pragma unroll 1
    for (int t0 = 0; t0 < TT; t0 += UU) {
        // Prefetch next group while processing current (keeps ~20 LDG in flight)
        const int tn = t0 + UU;
        if (tn < TT) {
            #pragma unroll
            for (int i = 0; i < UU; i++) nxt[i] = p[(size_t)(tn + i) * BN];
        }

        #pragma unroll
        for (int j = 0; j < UU; j++) {
            const int t = t0 + j;
            bool s = cur[j] > 0.5f;
            unsigned m = __ballot_sync(0xffffffffu, s);
            if (lane == 0) pop_s[w][t] = (float)__popc(m);
            if (s) {
                if (last >= 0) {
                    int g = t - last;
                    sumg2 += g * g;
                } else {
                    first = t;
                }
                last = t;
                total++;
            }
        }

        #pragma unroll
        for (int i = 0; i < UU; i++) cur[i] = nxt[i];
    }

    // Per-neuron outputs
    const int idx = b * NN + n;
    float tot = (float)total;
    out[OFF_FR + idx] = tot / (TT * 0.001f);   // firing rate (Hz)
    out[OFF_TS + idx] = tot;                   // total spikes

    float cv = 0.0f;
    int cnt = total - 1;                       // spikes with a predecessor
    if (cnt >= 1) {
        float fc   = (float)cnt;
        float mean = (float)(last - first) / fc;     // sum of gaps / cnt
        float var  = ((float)sumg2 - fc * mean * mean) / fmaxf(fc - 1.0f, 1.0f);
        cv = sqrtf(fmaxf(var, 0.0f)) / fmaxf(mean, 1e-12f);
    }
    out[OFF_CV + idx] = cv;

    // Active-neuron count: warp ballot -> block partial
    unsigned am = __ballot_sync(0xffffffffu, total > 0);
    if (lane == 0) active_s[w] = __popc(am);
    __syncthreads();
    if (tid == 0) {
        int a = 0;
        #pragma unroll
        for (int k = 0; k < 8; k++) a += active_s[k];
        g_active_part[bid] = (float)a;
    }

    // Reduce 8 warp rows -> per-block population partial
    #pragma unroll 1
    for (int t = tid; t < TT; t += 256) {
        float s = 0.0f;
        #pragma unroll
        for (int k = 0; k < 8; k++) s += pop_s[k][t];
        g_pop_part[bid * TT + t] = s;
    }
}

__global__ __launch_bounds__(256)
void spike_sync(float* __restrict__ out) {
    const int b   = blockIdx.x;    // 0..31
    const int tid = threadIdx.x;
    const int w   = tid >> 5;
    const int lane = tid & 31;

    __shared__ float  pop[TT];
    __shared__ double red_s[8];

    // Assemble pop[t] for this batch from the 8 block partials.
    // Fully unrolled: 4 t-iterations x 8 partials = 32 loads in flight.
    {
        float acc[4] = {0.f, 0.f, 0.f, 0.f};
        #pragma unroll
        for (int r = 0; r < 4; r++) {
            int t = tid + r * 256;
            if (t < TT) {
                #pragma unroll
                for (int k = 0; k < 8; k++)
                    acc[r] += g_pop_part[(b * 8 + k) * TT + t];
            }
        }
        #pragma unroll
        for (int r = 0; r < 4; r++) {
            int t = tid + r * 256;
            if (t < TT) pop[t] = acc[r];
        }
    }
    __syncthreads();

    // mean (shuffle-reduce, one barrier per stage)
    double ls = 0.0;
    #pragma unroll
    for (int r = 0; r < 4; r++) {
        int t = tid + r * 256;
        if (t < TT) ls += (double)pop[t];
    }
    #pragma unroll
    for (int o = 16; o > 0; o >>= 1) ls += __shfl_down_sync(0xffffffffu, ls, o);
    if (lane == 0) red_s[w] = ls;
    __syncthreads();
    double mean = 0.0;
    {
        double v = (tid < 8) ? red_s[tid] : 0.0;
        #pragma unroll
        for (int o = 4; o > 0; o >>= 1) v += __shfl_down_sync(0xffffffffu, v, o);
        if (tid == 0) red_s[0] = v / (double)TT;
    }
    __syncthreads();
    mean = red_s[0];
    __syncthreads();

    // circular lag-1 autocorr: num = sum xm[t]*xm[t-1], den = sum xm^2
    double lnum = 0.0, lden = 0.0;
    #pragma unroll
    for (int r = 0; r < 4; r++) {
        int t = tid + r * 256;
        if (t < TT) {
            double xm = (double)pop[t] - mean;
            int tp = (t == 0) ? (TT - 1) : (t - 1);
            double ym = (double)pop[tp] - mean;
            lnum += xm * ym;
            lden += xm * xm;
        }
    }
    #pragma unroll
    for (int o = 16; o > 0; o >>= 1) {
        lnum += __shfl_down_sync(0xffffffffu, lnum, o);
        lden += __shfl_down_sync(0xffffffffu, lden, o);
    }
    __shared__ double red2_s[8];
    if (lane == 0) { red_s[w] = lnum; red2_s[w] = lden; }
    __syncthreads();
    if (tid == 0) {
        double num = 0.0, den = 0.0;
        #pragma unroll
        for (int k = 0; k < 8; k++) { num += red_s[k]; den += red2_s[k]; }
        out[OFF_SY + b] = (den > 0.0) ? (float)(num / fmax(den, 1e-12)) : 0.0f;
        float a = 0.0f;
        #pragma unroll
        for (int k = 0; k < 8; k++) a += g_active_part[b * 8 + k];
        out[OFF_AN + b] = a;
    }
}

extern "C" void kernel_launch(void* const* d_in, const int* in_sizes, int n_in,
                              void* d_out, int out_size) {
    const float* in = (const float*)d_in[0];
    float* out = (float*)d_out;
    spike_main<<<256, 256>>>(in, out);
    spike_sync<<<BB, 256>>>(out);
}